// round 6
// baseline (speedup 1.0000x reference)
#include <cuda_runtime.h>
#include <cuda_bf16.h>
#include <math.h>

// Problem constants
#define T_STEPS 16384
#define D_IN    257
#define H_DIM   512
#define G4H     2048   // 4*H
#define O_DIM   257
#define REC_CTAS 128   // recurrence CTAs; each owns 4 hidden units
#define NREP    8      // replicas of the h-exchange buffer (spread L2 slices)

// Scratch (static __device__ arrays — no allocation allowed)
__device__ float    g_xg[(size_t)T_STEPS * G4H];   // 128 MB: precomputed input gates + biases
__device__ float    g_hs[(size_t)T_STEPS * H_DIM]; // 32 MB: h per timestep
// Tagged h exchange: [replica][parity][unit] -> (step_tag<<32)|float_bits
__device__ unsigned long long g_hx[NREP * 2 * H_DIM];

// ---------------------------------------------------------------------------
// init: reset exchange tags each launch (tags are monotonic within a launch)
// ---------------------------------------------------------------------------
__global__ void init_kernel() {
    const int idx = blockIdx.x * 256 + threadIdx.x;
    const int n = NREP * 2 * H_DIM;
    for (int i = idx; i < n; i += gridDim.x * 256) g_hx[i] = 0ull;
}

// ---------------------------------------------------------------------------
// Kernel A: x_gates[T, 4H] = stft @ W_ih^T + (b_ih + b_hh)
// ---------------------------------------------------------------------------
__global__ void __launch_bounds__(256) xgate_gemm(
    const float* __restrict__ stft, const float* __restrict__ W_ih,
    const float* __restrict__ b_ih, const float* __restrict__ b_hh)
{
    __shared__ float s_sh[16 * 260];  // row stride 260 (mult of 4 for float4)
    const int tid = threadIdx.x;
    const int t0  = blockIdx.x * 16;

    for (int r = 0; r < 16; r++)
        for (int d = tid; d < D_IN; d += 256)
            s_sh[r * 260 + d] = stft[(size_t)(t0 + r) * D_IN + d];
    __syncthreads();

    for (int cg = 0; cg < 8; cg++) {
        const int c = cg * 256 + tid;                  // 0..2047
        const float* wrow = W_ih + (size_t)c * D_IN;
        float acc[16];
        #pragma unroll
        for (int r = 0; r < 16; r++) acc[r] = 0.f;

        for (int dd = 0; dd < 64; dd++) {              // 64*4 = 256 of 257
            const float w0 = __ldg(wrow + dd * 4 + 0);
            const float w1 = __ldg(wrow + dd * 4 + 1);
            const float w2 = __ldg(wrow + dd * 4 + 2);
            const float w3 = __ldg(wrow + dd * 4 + 3);
            #pragma unroll
            for (int r = 0; r < 16; r++) {
                const float4 s4 = *reinterpret_cast<const float4*>(&s_sh[r * 260 + dd * 4]);
                float a = acc[r];
                a = fmaf(w0, s4.x, a);
                a = fmaf(w1, s4.y, a);
                a = fmaf(w2, s4.z, a);
                a = fmaf(w3, s4.w, a);
                acc[r] = a;
            }
        }
        const float wl = __ldg(wrow + 256);            // remainder d = 256
        #pragma unroll
        for (int r = 0; r < 16; r++) acc[r] = fmaf(wl, s_sh[r * 260 + 256], acc[r]);

        const float bias = __ldg(b_ih + c) + __ldg(b_hh + c);
        #pragma unroll
        for (int r = 0; r < 16; r++)
            g_xg[(size_t)(t0 + r) * G4H + c] = acc[r] + bias;
    }
}

// ---------------------------------------------------------------------------
// Kernel B: warp-specialized LSTM recurrence, persistent grid of 128 CTAs.
// Warps 0-3 (producers): warp w owns unit u0+w; dot -> warp shfl reduce ->
//   lane0 pointwise -> publish tagged 64-bit words to NREP replicas.
// Warps 4-7 (pollers): SENTINEL poll — spin on word 0 only (1 sector access
//   per iteration, 4x less LTS traffic than polling all 4 words), then fetch
//   and tag-verify the remaining 3 words. One __syncthreads per step.
// ---------------------------------------------------------------------------
__device__ __forceinline__ float fsigm(float x) { return 1.0f / (1.0f + __expf(-x)); }
__device__ __forceinline__ float ftanh(float x) { return 2.0f / (1.0f + __expf(-2.0f * x)) - 1.0f; }

__global__ void __launch_bounds__(256) lstm_rec(const float* __restrict__ W_hh)
{
    __shared__ float hbuf[2][H_DIM];   // double-buffered h (parity-indexed)

    const int tid = threadIdx.x;
    const int b   = blockIdx.x;
    const int w   = tid >> 5;
    const int l   = tid & 31;
    const int u0  = b * 4;

    // zero both h buffers (h_0 = 0)
    for (int i = tid; i < 2 * H_DIM; i += 256) (&hbuf[0][0])[i] = 0.f;

    if (w < 4) {
        // ---------------- producer warp: unit u = u0 + w ----------------
        const int u = u0 + w;
        // weights: [gate][chunk] -> W_hh[gt*512+u][c*128 + l*4 .. +3]
        float4 wv[4][4];
        #pragma unroll
        for (int gt = 0; gt < 4; gt++)
            #pragma unroll
            for (int c = 0; c < 4; c++)
                wv[gt][c] = __ldg(reinterpret_cast<const float4*>(
                    W_hh + (size_t)(gt * H_DIM + u) * H_DIM + c * 128 + l * 4));

        float cst = 0.f;
        // xg for current step, lane 0 only (4 gate rows)
        float xg0 = 0.f, xg1 = 0.f, xg2 = 0.f, xg3 = 0.f;
        if (l == 0) {
            xg0 = g_xg[0 * H_DIM + u];
            xg1 = g_xg[1 * H_DIM + u];
            xg2 = g_xg[2 * H_DIM + u];
            xg3 = g_xg[3 * H_DIM + u];
        }
        __syncthreads();

        for (int t = 0; t < T_STEPS; ++t) {
            // prefetch next step's xg (lane 0)
            float nx0 = 0.f, nx1 = 0.f, nx2 = 0.f, nx3 = 0.f;
            if (l == 0 && t + 1 < T_STEPS) {
                const float* xp = &g_xg[(size_t)(t + 1) * G4H + u];
                nx0 = __ldg(xp + 0 * H_DIM);
                nx1 = __ldg(xp + 1 * H_DIM);
                nx2 = __ldg(xp + 2 * H_DIM);
                nx3 = __ldg(xp + 3 * H_DIM);
            }

            // dot: 4 independent 16-deep FMA chains over smem h
            const float* hb = hbuf[t & 1];
            float a0 = 0.f, a1 = 0.f, a2 = 0.f, a3 = 0.f;
            #pragma unroll
            for (int c = 0; c < 4; c++) {
                const float4 h = *reinterpret_cast<const float4*>(&hb[c * 128 + l * 4]);
                const float4 q0 = wv[0][c], q1 = wv[1][c], q2 = wv[2][c], q3 = wv[3][c];
                a0 = fmaf(q0.x, h.x, a0); a0 = fmaf(q0.y, h.y, a0);
                a0 = fmaf(q0.z, h.z, a0); a0 = fmaf(q0.w, h.w, a0);
                a1 = fmaf(q1.x, h.x, a1); a1 = fmaf(q1.y, h.y, a1);
                a1 = fmaf(q1.z, h.z, a1); a1 = fmaf(q1.w, h.w, a1);
                a2 = fmaf(q2.x, h.x, a2); a2 = fmaf(q2.y, h.y, a2);
                a2 = fmaf(q2.z, h.z, a2); a2 = fmaf(q2.w, h.w, a2);
                a3 = fmaf(q3.x, h.x, a3); a3 = fmaf(q3.y, h.y, a3);
                a3 = fmaf(q3.z, h.z, a3); a3 = fmaf(q3.w, h.w, a3);
            }
            // warp butterfly reduce (4 values)
            #pragma unroll
            for (int off = 16; off > 0; off >>= 1) {
                a0 += __shfl_xor_sync(0xffffffffu, a0, off);
                a1 += __shfl_xor_sync(0xffffffffu, a1, off);
                a2 += __shfl_xor_sync(0xffffffffu, a2, off);
                a3 += __shfl_xor_sync(0xffffffffu, a3, off);
            }

            float hn = 0.f;
            if (l == 0) {
                const float ig = fsigm(a0 + xg0);
                const float ff = fsigm(a1 + xg1);
                const float gg = ftanh(a2 + xg2);
                const float oo = fsigm(a3 + xg3);
                cst = fmaf(ff, cst, ig * gg);
                hn = oo * ftanh(cst);
            }
            hn = __shfl_sync(0xffffffffu, hn, 0);

            // publish FIRST (critical path), then bookkeeping store
            if (l < 8) {
                const int par = (t + 1) & 1;
                const unsigned long long word =
                    ((unsigned long long)(unsigned)(t + 1) << 32) |
                    (unsigned long long)__float_as_uint(hn);
                unsigned long long* dst = &g_hx[((size_t)(l * 2 + par)) * H_DIM + u];
                asm volatile("st.global.relaxed.gpu.b64 [%0], %1;"
                             :: "l"(dst), "l"(word) : "memory");
            }
            if (l == 8) g_hs[(size_t)t * H_DIM + u] = hn;

            xg0 = nx0; xg1 = nx1; xg2 = nx2; xg3 = nx3;
            __syncthreads();
        }
    } else {
        // ---------------- poller threads: p = tid-128 polls producer CTA p --
        const int p    = tid - 128;            // 0..127
        const int crep = b & (NREP - 1);
        __syncthreads();                       // match producer pre-loop bar

        for (int t = 0; t < T_STEPS; ++t) {
            if (t + 1 < T_STEPS) {
                const unsigned tgt = (unsigned)(t + 1);
                const int par = (t + 1) & 1;
                unsigned long long* src =
                    &g_hx[((size_t)(crep * 2 + par)) * H_DIM + p * 4];
                unsigned long long v0, v1, v2, v3;
                // sentinel poll on word 0 only (low LTS traffic)
                while (true) {
                    asm volatile("ld.global.relaxed.gpu.b64 %0, [%1];"
                                 : "=l"(v0) : "l"(src) : "memory");
                    if ((unsigned)(v0 >> 32) == tgt) break;
                }
                // fetch + verify remaining 3 words (published simultaneously;
                // retries are rare)
                while (true) {
                    asm volatile("ld.global.relaxed.gpu.b64 %0, [%1];"
                                 : "=l"(v1) : "l"(src + 1) : "memory");
                    asm volatile("ld.global.relaxed.gpu.b64 %0, [%1];"
                                 : "=l"(v2) : "l"(src + 2) : "memory");
                    asm volatile("ld.global.relaxed.gpu.b64 %0, [%1];"
                                 : "=l"(v3) : "l"(src + 3) : "memory");
                    if ((unsigned)(v1 >> 32) == tgt && (unsigned)(v2 >> 32) == tgt &&
                        (unsigned)(v3 >> 32) == tgt)
                        break;
                }
                float4 hv;
                hv.x = __uint_as_float((unsigned)v0);
                hv.y = __uint_as_float((unsigned)v1);
                hv.z = __uint_as_float((unsigned)v2);
                hv.w = __uint_as_float((unsigned)v3);
                *reinterpret_cast<float4*>(&hbuf[par][p * 4]) = hv;
            }
            __syncthreads();
        }
    }
}

// ---------------------------------------------------------------------------
// Kernel C: out = log_softmax(hs @ W_out^T + b_out)
// ---------------------------------------------------------------------------
__global__ void __launch_bounds__(256) out_kernel(
    const float* __restrict__ W_out, const float* __restrict__ b_out,
    float* __restrict__ out)
{
    __shared__ float hsm[8 * 512];
    __shared__ float red[256];
    const int tid = threadIdx.x;
    const int t0  = blockIdx.x * 8;

    for (int idx = tid; idx < 8 * 512; idx += 256)
        hsm[idx] = g_hs[(size_t)t0 * H_DIM + idx];
    __syncthreads();

    float acc[8], acc2[8];
    #pragma unroll
    for (int r = 0; r < 8; r++) { acc[r] = 0.f; acc2[r] = 0.f; }

    const float4* wr = reinterpret_cast<const float4*>(W_out + (size_t)tid * H_DIM);
    for (int kk = 0; kk < 128; kk++) {
        const float4 w4 = __ldg(wr + kk);
        #pragma unroll
        for (int rr = 0; rr < 8; rr++) {
            const float4 hv = *reinterpret_cast<const float4*>(&hsm[rr * 512 + kk * 4]);
            float a = acc[rr];
            a = fmaf(w4.x, hv.x, a);
            a = fmaf(w4.y, hv.y, a);
            a = fmaf(w4.z, hv.z, a);
            a = fmaf(w4.w, hv.w, a);
            acc[rr] = a;
        }
    }
    if (tid == 0) {  // column 256
        const float4* wr2 = reinterpret_cast<const float4*>(W_out + (size_t)256 * H_DIM);
        for (int kk = 0; kk < 128; kk++) {
            const float4 w4 = __ldg(wr2 + kk);
            #pragma unroll
            for (int rr = 0; rr < 8; rr++) {
                const float4 hv = *reinterpret_cast<const float4*>(&hsm[rr * 512 + kk * 4]);
                float a = acc2[rr];
                a = fmaf(w4.x, hv.x, a);
                a = fmaf(w4.y, hv.y, a);
                a = fmaf(w4.z, hv.z, a);
                a = fmaf(w4.w, hv.w, a);
                acc2[rr] = a;
            }
        }
    }

    const float bias  = __ldg(b_out + tid);
    const float bias2 = __ldg(b_out + 256);

    for (int r = 0; r < 8; r++) {
        const float z  = acc[r] + bias;
        const float z2 = acc2[r] + bias2;          // meaningful only for tid==0
        float m = (tid == 0) ? fmaxf(z, z2) : z;

        red[tid] = m; __syncthreads();
        for (int s = 128; s > 0; s >>= 1) {
            if (tid < s) red[tid] = fmaxf(red[tid], red[tid + s]);
            __syncthreads();
        }
        const float mx = red[0]; __syncthreads();

        float e = __expf(z - mx);
        if (tid == 0) e += __expf(z2 - mx);
        red[tid] = e; __syncthreads();
        for (int s = 128; s > 0; s >>= 1) {
            if (tid < s) red[tid] += red[tid + s];
            __syncthreads();
        }
        const float lse = logf(red[0]); __syncthreads();

        out[(size_t)(t0 + r) * O_DIM + tid] = z - mx - lse;
        if (tid == 0) out[(size_t)(t0 + r) * O_DIM + 256] = z2 - mx - lse;
    }
}

// ---------------------------------------------------------------------------
// kernel_launch: init -> input GEMM -> recurrence -> output GEMM+softmax
// ---------------------------------------------------------------------------
extern "C" void kernel_launch(void* const* d_in, const int* in_sizes, int n_in,
                              void* d_out, int out_size)
{
    const float* stft  = (const float*)d_in[0];
    const float* W_ih  = (const float*)d_in[1];
    const float* W_hh  = (const float*)d_in[2];
    const float* b_ih  = (const float*)d_in[3];
    const float* b_hh  = (const float*)d_in[4];
    const float* W_out = (const float*)d_in[5];
    const float* b_out = (const float*)d_in[6];
    float* out = (float*)d_out;

    init_kernel<<<8, 256>>>();
    xgate_gemm<<<T_STEPS / 16, 256>>>(stft, W_ih, b_ih, b_hh);
    lstm_rec<<<REC_CTAS, 256>>>(W_hh);
    out_kernel<<<T_STEPS / 8, 256>>>(W_out, b_out, out);
}

// round 7
// speedup vs baseline: 1.7198x; 1.7198x over previous
#include <cuda_runtime.h>
#include <cuda_bf16.h>
#include <math.h>

// Problem constants
#define T_STEPS 16384
#define D_IN    257
#define H_DIM   512
#define G4H     2048   // 4*H
#define O_DIM   257
#define REC_CTAS 64    // recurrence CTAs; each owns 8 hidden units (32 gate rows)
#define NREP    8      // replicas of the h-exchange buffer (spread L2 slices)

// Scratch (static __device__ arrays — no allocation allowed)
__device__ float    g_xg[(size_t)T_STEPS * G4H];   // 128 MB: precomputed input gates + biases
__device__ float    g_hs[(size_t)T_STEPS * H_DIM]; // 32 MB: h per timestep
// Tagged h exchange: [replica][parity][unit] -> (step_tag<<32)|float_bits
__device__ unsigned long long g_hx[NREP * 2 * H_DIM];

// ---------------------------------------------------------------------------
// init: reset exchange tags each launch (tags are monotonic within a launch)
// ---------------------------------------------------------------------------
__global__ void init_kernel() {
    const int idx = blockIdx.x * 256 + threadIdx.x;
    const int n = NREP * 2 * H_DIM;
    for (int i = idx; i < n; i += gridDim.x * 256) g_hx[i] = 0ull;
}

// ---------------------------------------------------------------------------
// Kernel A: x_gates[T, 4H] = stft @ W_ih^T + (b_ih + b_hh)
// ---------------------------------------------------------------------------
__global__ void __launch_bounds__(256) xgate_gemm(
    const float* __restrict__ stft, const float* __restrict__ W_ih,
    const float* __restrict__ b_ih, const float* __restrict__ b_hh)
{
    __shared__ float s_sh[16 * 260];  // row stride 260 (mult of 4 for float4)
    const int tid = threadIdx.x;
    const int t0  = blockIdx.x * 16;

    for (int r = 0; r < 16; r++)
        for (int d = tid; d < D_IN; d += 256)
            s_sh[r * 260 + d] = stft[(size_t)(t0 + r) * D_IN + d];
    __syncthreads();

    for (int cg = 0; cg < 8; cg++) {
        const int c = cg * 256 + tid;                  // 0..2047
        const float* wrow = W_ih + (size_t)c * D_IN;
        float acc[16];
        #pragma unroll
        for (int r = 0; r < 16; r++) acc[r] = 0.f;

        for (int dd = 0; dd < 64; dd++) {              // 64*4 = 256 of 257
            const float w0 = __ldg(wrow + dd * 4 + 0);
            const float w1 = __ldg(wrow + dd * 4 + 1);
            const float w2 = __ldg(wrow + dd * 4 + 2);
            const float w3 = __ldg(wrow + dd * 4 + 3);
            #pragma unroll
            for (int r = 0; r < 16; r++) {
                const float4 s4 = *reinterpret_cast<const float4*>(&s_sh[r * 260 + dd * 4]);
                float a = acc[r];
                a = fmaf(w0, s4.x, a);
                a = fmaf(w1, s4.y, a);
                a = fmaf(w2, s4.z, a);
                a = fmaf(w3, s4.w, a);
                acc[r] = a;
            }
        }
        const float wl = __ldg(wrow + 256);            // remainder d = 256
        #pragma unroll
        for (int r = 0; r < 16; r++) acc[r] = fmaf(wl, s_sh[r * 260 + 256], acc[r]);

        const float bias = __ldg(b_ih + c) + __ldg(b_hh + c);
        #pragma unroll
        for (int r = 0; r < 16; r++)
            g_xg[(size_t)(t0 + r) * G4H + c] = acc[r] + bias;
    }
}

// ---------------------------------------------------------------------------
// Kernel B: LSTM recurrence, persistent 64 CTAs x 256 threads.
// CTA b owns units u0=8b..8b+7 (32 gate rows). Thread (warp w, lane l):
//   row = l (gate=l>>3, unit=l&7), k-segment = w (64 k-values, 16 float4 regs).
// Phases: dot -> red[] -> bar1 -> warp0: 8-way sum + xg + shfl-gather ->
//   redundant pointwise in all 32 lanes -> publish (2 stores/lane, 8 replicas)
//   meanwhile warps 4-7 poll other CTAs' tagged words -> bar2.
// Double-buffered smem h by parity; 2 barriers/step.
// ---------------------------------------------------------------------------
__device__ __forceinline__ float fsigm(float x) { return 1.0f / (1.0f + __expf(-x)); }
__device__ __forceinline__ float ftanh(float x) { return 2.0f / (1.0f + __expf(-2.0f * x)) - 1.0f; }

__global__ void __launch_bounds__(256) lstm_rec(const float* __restrict__ W_hh)
{
    __shared__ float hbuf[2][H_DIM];   // double-buffered h (parity-indexed)
    __shared__ float red[8 * 32];      // per-warp row partials

    const int tid = threadIdx.x;
    const int b   = blockIdx.x;        // 0..63
    const int w   = tid >> 5;
    const int l   = tid & 31;
    const int u0  = b * 8;
    const int un  = l & 7;                         // unit within CTA
    const int rowg = (l >> 3) * H_DIM + u0 + un;   // global gate row (l = row)

    // weights: row rowg, k in [w*64, w*64+64) -> 16 float4 in registers
    float4 wv[16];
    {
        const float4* wp = reinterpret_cast<const float4*>(
            W_hh + (size_t)rowg * H_DIM + (size_t)w * 64);
        #pragma unroll
        for (int i = 0; i < 16; i++) wv[i] = __ldg(wp + i);
    }

    // zero both h buffers (h_0 = 0)
    for (int i = tid; i < 2 * H_DIM; i += 256) (&hbuf[0][0])[i] = 0.f;

    float cst = 0.f;                   // c state (warp 0, per-lane for unit un)
    float xgr = (w == 0) ? g_xg[rowg] : 0.f;   // xg for step 0 (warp 0 lanes)
    __syncthreads();

    for (int t = 0; t < T_STEPS; ++t) {
        // prefetch next step's xg (warp 0)
        float nx = 0.f;
        if (w == 0 && t + 1 < T_STEPS)
            nx = __ldg(&g_xg[(size_t)(t + 1) * G4H + rowg]);

        // dot: 64 k-values from smem h (broadcast reads), 4 accumulators
        const float4* hb = reinterpret_cast<const float4*>(&hbuf[t & 1][w * 64]);
        float a0 = 0.f, a1 = 0.f, a2 = 0.f, a3 = 0.f;
        #pragma unroll
        for (int i = 0; i < 4; i++) {
            float4 h, q;
            h = hb[i * 4 + 0]; q = wv[i * 4 + 0];
            a0 = fmaf(q.x, h.x, a0); a0 = fmaf(q.y, h.y, a0);
            a0 = fmaf(q.z, h.z, a0); a0 = fmaf(q.w, h.w, a0);
            h = hb[i * 4 + 1]; q = wv[i * 4 + 1];
            a1 = fmaf(q.x, h.x, a1); a1 = fmaf(q.y, h.y, a1);
            a1 = fmaf(q.z, h.z, a1); a1 = fmaf(q.w, h.w, a1);
            h = hb[i * 4 + 2]; q = wv[i * 4 + 2];
            a2 = fmaf(q.x, h.x, a2); a2 = fmaf(q.y, h.y, a2);
            a2 = fmaf(q.z, h.z, a2); a2 = fmaf(q.w, h.w, a2);
            h = hb[i * 4 + 3]; q = wv[i * 4 + 3];
            a3 = fmaf(q.x, h.x, a3); a3 = fmaf(q.y, h.y, a3);
            a3 = fmaf(q.z, h.z, a3); a3 = fmaf(q.w, h.w, a3);
        }
        red[w * 32 + l] = (a0 + a1) + (a2 + a3);
        __syncthreads();   // bar1: red[] complete

        const int par = (t + 1) & 1;

        if (tid < 32) {
            // ---- warp 0: reduce + gather + pointwise + publish ----
            float g = xgr;
            #pragma unroll
            for (int ww = 0; ww < 8; ww++) g += red[ww * 32 + l];
            const unsigned FULL = 0xffffffffu;
            const float vi = __shfl_sync(FULL, g, un);
            const float vf = __shfl_sync(FULL, g, 8 + un);
            const float vg = __shfl_sync(FULL, g, 16 + un);
            const float vo = __shfl_sync(FULL, g, 24 + un);
            // redundant pointwise in all 32 lanes (identical per un group)
            const float ig = fsigm(vi);
            const float ff = fsigm(vf);
            const float gg = ftanh(vg);
            const float oo = fsigm(vo);
            cst = fmaf(ff, cst, ig * gg);
            const float hn = oo * ftanh(cst);
            // publish: lane l -> replicas (l>>3) and (l>>3)+4 for unit un
            const unsigned long long word =
                ((unsigned long long)(unsigned)(t + 1) << 32) |
                (unsigned long long)__float_as_uint(hn);
            const int rep = l >> 3;
            unsigned long long* d1 = &g_hx[((size_t)(rep * 2 + par)) * H_DIM + u0 + un];
            unsigned long long* d2 = &g_hx[((size_t)((rep + 4) * 2 + par)) * H_DIM + u0 + un];
            asm volatile("st.global.relaxed.gpu.b64 [%0], %1;" :: "l"(d1), "l"(word) : "memory");
            asm volatile("st.global.relaxed.gpu.b64 [%0], %1;" :: "l"(d2), "l"(word) : "memory");
            if (l < 8) g_hs[(size_t)t * H_DIM + u0 + un] = hn;
            xgr = nx;
        } else if (tid >= 128 && t + 1 < T_STEPS) {
            // ---- warps 4-7: poll group p (4 consecutive units, one producer)
            const int p    = tid - 128;           // 0..127
            const int crep = b & (NREP - 1);
            const unsigned tgt = (unsigned)(t + 1);
            unsigned long long* src =
                &g_hx[((size_t)(crep * 2 + par)) * H_DIM + p * 4];
            unsigned long long v0, v1, v2, v3;
            while (true) {
                asm volatile("ld.global.relaxed.gpu.b64 %0, [%1];"
                             : "=l"(v0) : "l"(src) : "memory");
                asm volatile("ld.global.relaxed.gpu.b64 %0, [%1];"
                             : "=l"(v1) : "l"(src + 1) : "memory");
                asm volatile("ld.global.relaxed.gpu.b64 %0, [%1];"
                             : "=l"(v2) : "l"(src + 2) : "memory");
                asm volatile("ld.global.relaxed.gpu.b64 %0, [%1];"
                             : "=l"(v3) : "l"(src + 3) : "memory");
                if ((unsigned)(v0 >> 32) == tgt && (unsigned)(v1 >> 32) == tgt &&
                    (unsigned)(v2 >> 32) == tgt && (unsigned)(v3 >> 32) == tgt)
                    break;
            }
            float4 hv;
            hv.x = __uint_as_float((unsigned)v0);
            hv.y = __uint_as_float((unsigned)v1);
            hv.z = __uint_as_float((unsigned)v2);
            hv.w = __uint_as_float((unsigned)v3);
            *reinterpret_cast<float4*>(&hbuf[par][p * 4]) = hv;
        }
        __syncthreads();   // bar2: next-step h ready
    }
}

// ---------------------------------------------------------------------------
// Kernel C: out = log_softmax(hs @ W_out^T + b_out)
// ---------------------------------------------------------------------------
__global__ void __launch_bounds__(256) out_kernel(
    const float* __restrict__ W_out, const float* __restrict__ b_out,
    float* __restrict__ out)
{
    __shared__ float hsm[8 * 512];
    __shared__ float red[256];
    const int tid = threadIdx.x;
    const int t0  = blockIdx.x * 8;

    for (int idx = tid; idx < 8 * 512; idx += 256)
        hsm[idx] = g_hs[(size_t)t0 * H_DIM + idx];
    __syncthreads();

    float acc[8], acc2[8];
    #pragma unroll
    for (int r = 0; r < 8; r++) { acc[r] = 0.f; acc2[r] = 0.f; }

    const float4* wr = reinterpret_cast<const float4*>(W_out + (size_t)tid * H_DIM);
    for (int kk = 0; kk < 128; kk++) {
        const float4 w4 = __ldg(wr + kk);
        #pragma unroll
        for (int rr = 0; rr < 8; rr++) {
            const float4 hv = *reinterpret_cast<const float4*>(&hsm[rr * 512 + kk * 4]);
            float a = acc[rr];
            a = fmaf(w4.x, hv.x, a);
            a = fmaf(w4.y, hv.y, a);
            a = fmaf(w4.z, hv.z, a);
            a = fmaf(w4.w, hv.w, a);
            acc[rr] = a;
        }
    }
    if (tid == 0) {  // column 256
        const float4* wr2 = reinterpret_cast<const float4*>(W_out + (size_t)256 * H_DIM);
        for (int kk = 0; kk < 128; kk++) {
            const float4 w4 = __ldg(wr2 + kk);
            #pragma unroll
            for (int rr = 0; rr < 8; rr++) {
                const float4 hv = *reinterpret_cast<const float4*>(&hsm[rr * 512 + kk * 4]);
                float a = acc2[rr];
                a = fmaf(w4.x, hv.x, a);
                a = fmaf(w4.y, hv.y, a);
                a = fmaf(w4.z, hv.z, a);
                a = fmaf(w4.w, hv.w, a);
                acc2[rr] = a;
            }
        }
    }

    const float bias  = __ldg(b_out + tid);
    const float bias2 = __ldg(b_out + 256);

    for (int r = 0; r < 8; r++) {
        const float z  = acc[r] + bias;
        const float z2 = acc2[r] + bias2;          // meaningful only for tid==0
        float m = (tid == 0) ? fmaxf(z, z2) : z;

        red[tid] = m; __syncthreads();
        for (int s = 128; s > 0; s >>= 1) {
            if (tid < s) red[tid] = fmaxf(red[tid], red[tid + s]);
            __syncthreads();
        }
        const float mx = red[0]; __syncthreads();

        float e = __expf(z - mx);
        if (tid == 0) e += __expf(z2 - mx);
        red[tid] = e; __syncthreads();
        for (int s = 128; s > 0; s >>= 1) {
            if (tid < s) red[tid] += red[tid + s];
            __syncthreads();
        }
        const float lse = logf(red[0]); __syncthreads();

        out[(size_t)(t0 + r) * O_DIM + tid] = z - mx - lse;
        if (tid == 0) out[(size_t)(t0 + r) * O_DIM + 256] = z2 - mx - lse;
    }
}

// ---------------------------------------------------------------------------
// kernel_launch: init -> input GEMM -> recurrence -> output GEMM+softmax
// ---------------------------------------------------------------------------
extern "C" void kernel_launch(void* const* d_in, const int* in_sizes, int n_in,
                              void* d_out, int out_size)
{
    const float* stft  = (const float*)d_in[0];
    const float* W_ih  = (const float*)d_in[1];
    const float* W_hh  = (const float*)d_in[2];
    const float* b_ih  = (const float*)d_in[3];
    const float* b_hh  = (const float*)d_in[4];
    const float* W_out = (const float*)d_in[5];
    const float* b_out = (const float*)d_in[6];
    float* out = (float*)d_out;

    init_kernel<<<8, 256>>>();
    xgate_gemm<<<T_STEPS / 16, 256>>>(stft, W_ih, b_ih, b_hh);
    lstm_rec<<<REC_CTAS, 256>>>(W_hh);
    out_kernel<<<T_STEPS / 8, 256>>>(W_out, b_out, out);
}